// round 2
// baseline (speedup 1.0000x reference)
#include <cuda_runtime.h>

// ---------------- problem constants ----------------
#define BB   2
#define CC   24
#define KQ   7
#define KK   49            // KQ*KQ
#define HH   256
#define WW   256
#define CO   1176          // CC*KK
#define PLANE 65536        // HH*WW
#define NPIX  131072       // BB*PLANE

// ---------------- device scratch (no allocs allowed) ----------------
__device__ float g_E[(size_t)CO * NPIX];   // unnormalized exp(logits), plane-major: [o][b*PLANE + y*W + x]
__device__ float g_Sinv[NPIX];             // 1/sum(exp) per pixel
__device__ float g_lat[BB * CC * PLANE];   // depth_latent
__device__ float g_dA[BB * CC * PLANE];    // diffusion ping
__device__ float g_dB[BB * CC * PLANE];    // diffusion pong

// ================= K1: depth_latent = conv3x3(depth; 1 -> 24) =================
__global__ void k_lat(const float* __restrict__ depth,
                      const float* __restrict__ w_dp,
                      const float* __restrict__ b_dp) {
    __shared__ float sD[3][WW + 2];
    __shared__ float sW[CC * 9];
    __shared__ float sB[CC];
    const int bid = blockIdx.x;          // b*HH + y
    const int b = bid >> 8, y = bid & 255;
    const int tid = threadIdx.x;

    for (int i = tid; i < CC * 9; i += blockDim.x) sW[i] = w_dp[i];
    if (tid < CC) sB[tid] = b_dp[tid];

    const float* dp = depth + (size_t)b * PLANE;
    for (int r = 0; r < 3; r++) {
        const int yy = y + r - 1;
        for (int xx = tid; xx < WW + 2; xx += blockDim.x) {
            const int gx = xx - 1;
            sD[r][xx] = (yy >= 0 && yy < HH && gx >= 0 && gx < WW) ? dp[yy * WW + gx] : 0.f;
        }
    }
    __syncthreads();

    float p[9];
#pragma unroll
    for (int r = 0; r < 3; r++)
#pragma unroll
        for (int cx = 0; cx < 3; cx++) p[r * 3 + cx] = sD[r][tid + cx];

    for (int co = 0; co < CC; co++) {
        float acc = sB[co];
#pragma unroll
        for (int j = 0; j < 9; j++) acc = fmaf(sW[co * 9 + j], p[j], acc);
        g_lat[((size_t)(b * CC + co) * HH + y) * WW + tid] = acc;
    }
}

// ================= K2: logits conv (3 -> 1176) + exp + per-pixel sum =================
// One block per image row (256 pixels), one thread per pixel.
// Weights staged through smem in 4 chunks of 294 outputs (fits 48KB static smem).
#define OCHUNK 294
__global__ void k_softmax(const float* __restrict__ tex,
                          const float* __restrict__ w_kp,
                          const float* __restrict__ b_kp) {
    __shared__ __align__(16) float sW[OCHUNK * 28];   // 27 weights + 1 pad per output
    __shared__ float sT[3][3][WW + 2];

    const int bid = blockIdx.x;          // b*HH + y
    const int b = bid >> 8, y = bid & 255;
    const int tid = threadIdx.x;

    // stage texture rows (3 channels, rows y-1..y+1, zero-padded)
    for (int ch = 0; ch < 3; ch++) {
        const float* tp = tex + (size_t)(b * 3 + ch) * PLANE;
        for (int r = 0; r < 3; r++) {
            const int yy = y + r - 1;
            for (int xx = tid; xx < WW + 2; xx += blockDim.x) {
                const int gx = xx - 1;
                sT[ch][r][xx] = (yy >= 0 && yy < HH && gx >= 0 && gx < WW) ? tp[yy * WW + gx] : 0.f;
            }
        }
    }

    float p[27];
    float S = 0.f;
    const size_t pix = (size_t)b * PLANE + (size_t)y * WW + tid;
    bool first = true;

    for (int ochunk = 0; ochunk < CO; ochunk += OCHUNK) {
        __syncthreads();   // previous chunk fully consumed; (first iter: sT writes done)
        for (int i = tid; i < OCHUNK * 27; i += blockDim.x) {
            const int o = i / 27, j = i - o * 27;
            sW[o * 28 + j] = w_kp[(size_t)(ochunk + o) * 27 + j];
        }
        __syncthreads();

        if (first) {
#pragma unroll
            for (int ch = 0; ch < 3; ch++)
#pragma unroll
                for (int r = 0; r < 3; r++)
#pragma unroll
                    for (int cx = 0; cx < 3; cx++)
                        p[(ch * 3 + r) * 3 + cx] = sT[ch][r][tid + cx];
            first = false;
        }

        for (int ol = 0; ol < OCHUNK; ol++) {
            float wr[28];
            float4* wr4 = reinterpret_cast<float4*>(wr);
            const float4* src4 = reinterpret_cast<const float4*>(&sW[ol * 28]);
#pragma unroll
            for (int q = 0; q < 7; q++) wr4[q] = src4[q];

            float a0 = b_kp[ochunk + ol], a1 = 0.f, a2 = 0.f, a3 = 0.f;
#pragma unroll
            for (int j = 0; j < 27; j += 4) {
                a0 = fmaf(wr[j], p[j], a0);
                if (j + 1 < 27) a1 = fmaf(wr[j + 1], p[j + 1], a1);
                if (j + 2 < 27) a2 = fmaf(wr[j + 2], p[j + 2], a2);
                if (j + 3 < 27) a3 = fmaf(wr[j + 3], p[j + 3], a3);
            }
            const float e = __expf((a0 + a1) + (a2 + a3));
            S += e;
            g_E[(size_t)(ochunk + ol) * NPIX + pix] = e;
        }
    }
    g_Sinv[pix] = 1.f / S;
}

// ================= K3..K6: one diffusion iteration =================
// diffused[c](p) = (sum_t E[c*49+t](p) * in[c](p + delta_t)) * Sinv(p)
// Block: 256 threads = one x-row span; handles RROWS rows of one (b, c) plane.
#define RROWS 8
__global__ void k_diff(int srcSel, int dstSel) {
    __shared__ float sIn[RROWS + 6][WW + 8];
    const int tid = threadIdx.x;
    const int ty = blockIdx.x;           // 0..HH/RROWS-1
    const int c = blockIdx.y;
    const int b = blockIdx.z;
    const int y0 = ty * RROWS;

    const float* src = (srcSel == 0) ? g_lat : (srcSel == 1 ? g_dA : g_dB);
    float* dst = (dstSel == 1) ? g_dA : g_dB;

    const float* sp = src + (size_t)(b * CC + c) * PLANE;
    for (int r = 0; r < RROWS + 6; r++) {
        const int yy = y0 + r - 3;
        for (int xx = tid; xx < WW + 6; xx += blockDim.x) {
            const int gx = xx - 3;
            sIn[r][xx] = (yy >= 0 && yy < HH && gx >= 0 && gx < WW) ? sp[yy * WW + gx] : 0.f;
        }
    }
    __syncthreads();

    const float* Ebase = g_E + (size_t)(c * KK) * NPIX + (size_t)b * PLANE + (size_t)y0 * WW + tid;
    const float* Sp = g_Sinv + (size_t)b * PLANE + (size_t)y0 * WW + tid;
    float* dp = dst + ((size_t)(b * CC + c) * HH + y0) * WW + tid;

    for (int ry = 0; ry < RROWS; ry++) {
        const float* Ep = Ebase + (size_t)ry * WW;
        float acc0 = 0.f, acc1 = 0.f;
#pragma unroll
        for (int t = 0; t < KK; t++) {
            const float ev = Ep[(size_t)t * NPIX];
            const float dv = sIn[ry + t / KQ][tid + t % KQ];
            if (t & 1) acc1 = fmaf(ev, dv, acc1);
            else       acc0 = fmaf(ev, dv, acc0);
        }
        dp[(size_t)ry * WW] = (acc0 + acc1) * Sp[(size_t)ry * WW];
    }
}

// ================= K7: 1x1 conv (24 -> 1) =================
__global__ void k_out(const float* __restrict__ w_td,
                      const float* __restrict__ b_td,
                      float* __restrict__ out) {
    const int bid = blockIdx.x;          // b*HH + y
    const int b = bid >> 8, y = bid & 255;
    const int tid = threadIdx.x;
    const float* sp = g_dB + (size_t)b * CC * PLANE + (size_t)y * WW + tid;
    float acc = b_td[0];
#pragma unroll
    for (int c = 0; c < CC; c++) acc = fmaf(w_td[c], sp[(size_t)c * PLANE], acc);
    out[(size_t)b * PLANE + (size_t)y * WW + tid] = acc;
}

// ================= host launcher =================
extern "C" void kernel_launch(void* const* d_in, const int* in_sizes, int n_in,
                              void* d_out, int out_size) {
    const float* depth   = (const float*)d_in[0];
    const float* texture = (const float*)d_in[1];
    const float* w_dp    = (const float*)d_in[2];
    const float* b_dp    = (const float*)d_in[3];
    const float* w_kp    = (const float*)d_in[4];
    const float* b_kp    = (const float*)d_in[5];
    const float* w_td    = (const float*)d_in[6];
    const float* b_td    = (const float*)d_in[7];
    float* out = (float*)d_out;

    k_lat<<<BB * HH, 256>>>(depth, w_dp, b_dp);
    k_softmax<<<BB * HH, 256>>>(texture, w_kp, b_kp);

    dim3 gd(HH / RROWS, CC, BB);
    k_diff<<<gd, 256>>>(0, 1);   // lat -> dA
    k_diff<<<gd, 256>>>(1, 2);   // dA  -> dB
    k_diff<<<gd, 256>>>(2, 1);   // dB  -> dA
    k_diff<<<gd, 256>>>(1, 2);   // dA  -> dB

    k_out<<<BB * HH, 256>>>(w_td, b_td, out);
}

// round 3
// speedup vs baseline: 1.1240x; 1.1240x over previous
#include <cuda_runtime.h>
#include <cuda_fp16.h>

// ---------------- problem constants ----------------
#define BB   2
#define CC   24
#define KQ   7
#define KK   49            // KQ*KQ
#define HH   256
#define WW   256
#define CO   1176          // CC*KK
#define PLANE 65536        // HH*WW
#define NPIX  131072       // BB*PLANE

// ---------------- device scratch (no allocs allowed) ----------------
__device__ __half g_E[(size_t)CO * NPIX];  // unnormalized exp(logits), fp16, plane-major
__device__ float g_Sinv[NPIX];             // 1/sum(exp) per pixel (sum of ROUNDED halves)
__device__ float g_lat[BB * CC * PLANE];   // depth_latent
__device__ float g_dA[BB * CC * PLANE];    // diffusion ping
__device__ float g_dB[BB * CC * PLANE];    // diffusion pong

// ---------------- packed f32x2 helpers ----------------
__device__ __forceinline__ unsigned long long pk2(float lo, float hi) {
    unsigned long long r;
    asm("mov.b64 %0, {%1, %2};" : "=l"(r) : "f"(lo), "f"(hi));
    return r;
}
__device__ __forceinline__ void fma2(unsigned long long& d, unsigned long long a, unsigned long long b) {
    asm("fma.rn.f32x2 %0, %1, %2, %0;" : "+l"(d) : "l"(a), "l"(b));
}
__device__ __forceinline__ void add2(unsigned long long& d, unsigned long long a) {
    asm("add.rn.f32x2 %0, %0, %1;" : "+l"(d) : "l"(a));
}
__device__ __forceinline__ void unpk2(float& lo, float& hi, unsigned long long v) {
    asm("mov.b64 {%0, %1}, %2;" : "=f"(lo), "=f"(hi) : "l"(v));
}

// ================= K1: depth_latent = conv3x3(depth; 1 -> 24) =================
__global__ void k_lat(const float* __restrict__ depth,
                      const float* __restrict__ w_dp,
                      const float* __restrict__ b_dp) {
    __shared__ float sD[3][WW + 2];
    __shared__ float sW[CC * 9];
    __shared__ float sB[CC];
    const int bid = blockIdx.x;          // b*HH + y
    const int b = bid >> 8, y = bid & 255;
    const int tid = threadIdx.x;

    for (int i = tid; i < CC * 9; i += blockDim.x) sW[i] = w_dp[i];
    if (tid < CC) sB[tid] = b_dp[tid];

    const float* dp = depth + (size_t)b * PLANE;
    for (int r = 0; r < 3; r++) {
        const int yy = y + r - 1;
        for (int xx = tid; xx < WW + 2; xx += blockDim.x) {
            const int gx = xx - 1;
            sD[r][xx] = (yy >= 0 && yy < HH && gx >= 0 && gx < WW) ? dp[yy * WW + gx] : 0.f;
        }
    }
    __syncthreads();

    float p[9];
#pragma unroll
    for (int r = 0; r < 3; r++)
#pragma unroll
        for (int cx = 0; cx < 3; cx++) p[r * 3 + cx] = sD[r][tid + cx];

    for (int co = 0; co < CC; co++) {
        float acc = sB[co];
#pragma unroll
        for (int j = 0; j < 9; j++) acc = fmaf(sW[co * 9 + j], p[j], acc);
        g_lat[((size_t)(b * CC + co) * HH + y) * WW + tid] = acc;
    }
}

// ================= K2: logits conv (3 -> 1176) + exp (fp16 out) + per-pixel sum =================
// 128 threads per block, one image row; each thread computes the PIXEL PAIR (2*tid, 2*tid+1)
// using packed f32x2 FMA. Weights staged in smem duplicated as (w, w) pairs so the packed
// operands come straight out of LDS.128 as aligned register pairs.
#define OCHUNK 168           // 1176 / 168 = 7 chunks
__global__ void k_softmax(const float* __restrict__ tex,
                          const float* __restrict__ w_kp,
                          const float* __restrict__ b_kp) {
    __shared__ __align__(16) float2 sW2[OCHUNK * 28];   // (w,w) pairs, 27 + 1 zero-pad per output
    __shared__ float sB[OCHUNK];
    __shared__ float sT[3][3][WW + 2];

    const int bid = blockIdx.x;          // b*HH + y
    const int b = bid >> 8, y = bid & 255;
    const int tid = threadIdx.x;         // 0..127

    // stage texture rows (3 channels, rows y-1..y+1, zero-padded)
    for (int ch = 0; ch < 3; ch++) {
        const float* tp = tex + (size_t)(b * 3 + ch) * PLANE;
        for (int r = 0; r < 3; r++) {
            const int yy = y + r - 1;
            for (int xx = tid; xx < WW + 2; xx += blockDim.x) {
                const int gx = xx - 1;
                sT[ch][r][xx] = (yy >= 0 && yy < HH && gx >= 0 && gx < WW) ? tp[yy * WW + gx] : 0.f;
            }
        }
    }
    __syncthreads();

    // build packed patch for the pixel pair (x0 = 2*tid, x0+1)
    unsigned long long p2[28];
    const int x0 = 2 * tid;
#pragma unroll
    for (int ch = 0; ch < 3; ch++)
#pragma unroll
        for (int r = 0; r < 3; r++)
#pragma unroll
            for (int cx = 0; cx < 3; cx++)
                p2[(ch * 3 + r) * 3 + cx] = pk2(sT[ch][r][x0 + cx], sT[ch][r][x0 + 1 + cx]);
    p2[27] = pk2(0.f, 0.f);

    float S0 = 0.f, S1 = 0.f;
    const size_t pixbase = (size_t)b * PLANE + (size_t)y * WW + x0;   // even

    for (int ochunk = 0; ochunk < CO; ochunk += OCHUNK) {
        __syncthreads();   // previous chunk fully consumed
        for (int i = tid; i < OCHUNK * 28; i += blockDim.x) {
            const int o = i / 28, j = i - o * 28;
            const float w = (j < 27) ? w_kp[(size_t)(ochunk + o) * 27 + j] : 0.f;
            sW2[o * 28 + j] = make_float2(w, w);
        }
        for (int i = tid; i < OCHUNK; i += blockDim.x) sB[i] = b_kp[ochunk + i];
        __syncthreads();

        for (int ol = 0; ol < OCHUNK; ol++) {
            const float4* w4 = reinterpret_cast<const float4*>(&sW2[ol * 28]);
            const float bia = sB[ol];
            unsigned long long a0 = pk2(bia, bia);
            unsigned long long a1 = pk2(0.f, 0.f);
            unsigned long long a2 = pk2(0.f, 0.f);
            unsigned long long a3 = pk2(0.f, 0.f);
#pragma unroll
            for (int q = 0; q < 14; q += 2) {
                float4 v0 = w4[q];
                float4 v1 = w4[q + 1];
                fma2(a0, pk2(v0.x, v0.y), p2[2 * q + 0]);
                fma2(a1, pk2(v0.z, v0.w), p2[2 * q + 1]);
                fma2(a2, pk2(v1.x, v1.y), p2[2 * q + 2]);
                fma2(a3, pk2(v1.z, v1.w), p2[2 * q + 3]);
            }
            add2(a0, a1);
            add2(a2, a3);
            add2(a0, a2);
            float l0, l1;
            unpk2(l0, l1, a0);
            const __half2 h = __floats2half2_rn(__expf(l0), __expf(l1));
            const float2 er = __half22float2(h);   // accumulate the ROUNDED values
            S0 += er.x;
            S1 += er.y;
            *reinterpret_cast<__half2*>(&g_E[(size_t)(ochunk + ol) * NPIX + pixbase]) = h;
        }
    }
    g_Sinv[pixbase]     = 1.f / S0;
    g_Sinv[pixbase + 1] = 1.f / S1;
}

// ================= K3..K6: one diffusion iteration (fp16 E reads) =================
#define RROWS 8
__global__ void k_diff(int srcSel, int dstSel) {
    __shared__ float sIn[RROWS + 6][WW + 8];
    const int tid = threadIdx.x;
    const int ty = blockIdx.x;           // 0..HH/RROWS-1
    const int c = blockIdx.y;
    const int b = blockIdx.z;
    const int y0 = ty * RROWS;

    const float* src = (srcSel == 0) ? g_lat : (srcSel == 1 ? g_dA : g_dB);
    float* dst = (dstSel == 1) ? g_dA : g_dB;

    const float* sp = src + (size_t)(b * CC + c) * PLANE;
    for (int r = 0; r < RROWS + 6; r++) {
        const int yy = y0 + r - 3;
        for (int xx = tid; xx < WW + 6; xx += blockDim.x) {
            const int gx = xx - 3;
            sIn[r][xx] = (yy >= 0 && yy < HH && gx >= 0 && gx < WW) ? sp[yy * WW + gx] : 0.f;
        }
    }
    __syncthreads();

    const __half* Ebase = g_E + (size_t)(c * KK) * NPIX + (size_t)b * PLANE + (size_t)y0 * WW + tid;
    const float* Sp = g_Sinv + (size_t)b * PLANE + (size_t)y0 * WW + tid;
    float* dp = dst + ((size_t)(b * CC + c) * HH + y0) * WW + tid;

    for (int ry = 0; ry < RROWS; ry++) {
        const __half* Ep = Ebase + (size_t)ry * WW;
        float acc0 = 0.f, acc1 = 0.f;
#pragma unroll
        for (int t = 0; t < KK; t++) {
            const float ev = __half2float(Ep[(size_t)t * NPIX]);
            const float dv = sIn[ry + t / KQ][tid + t % KQ];
            if (t & 1) acc1 = fmaf(ev, dv, acc1);
            else       acc0 = fmaf(ev, dv, acc0);
        }
        dp[(size_t)ry * WW] = (acc0 + acc1) * Sp[(size_t)ry * WW];
    }
}

// ================= K7: 1x1 conv (24 -> 1) =================
__global__ void k_out(const float* __restrict__ w_td,
                      const float* __restrict__ b_td,
                      float* __restrict__ out) {
    const int bid = blockIdx.x;          // b*HH + y
    const int b = bid >> 8, y = bid & 255;
    const int tid = threadIdx.x;
    const float* sp = g_dB + (size_t)b * CC * PLANE + (size_t)y * WW + tid;
    float acc = b_td[0];
#pragma unroll
    for (int c = 0; c < CC; c++) acc = fmaf(w_td[c], sp[(size_t)c * PLANE], acc);
    out[(size_t)b * PLANE + (size_t)y * WW + tid] = acc;
}

// ================= host launcher =================
extern "C" void kernel_launch(void* const* d_in, const int* in_sizes, int n_in,
                              void* d_out, int out_size) {
    const float* depth   = (const float*)d_in[0];
    const float* texture = (const float*)d_in[1];
    const float* w_dp    = (const float*)d_in[2];
    const float* b_dp    = (const float*)d_in[3];
    const float* w_kp    = (const float*)d_in[4];
    const float* b_kp    = (const float*)d_in[5];
    const float* w_td    = (const float*)d_in[6];
    const float* b_td    = (const float*)d_in[7];
    float* out = (float*)d_out;

    k_lat<<<BB * HH, 256>>>(depth, w_dp, b_dp);
    k_softmax<<<BB * HH, 128>>>(texture, w_kp, b_kp);

    dim3 gd(HH / RROWS, CC, BB);
    k_diff<<<gd, 256>>>(0, 1);   // lat -> dA
    k_diff<<<gd, 256>>>(1, 2);   // dA  -> dB
    k_diff<<<gd, 256>>>(2, 1);   // dB  -> dA
    k_diff<<<gd, 256>>>(1, 2);   // dA  -> dB

    k_out<<<BB * HH, 256>>>(w_td, b_td, out);
}

// round 4
// speedup vs baseline: 1.2150x; 1.0809x over previous
#include <cuda_runtime.h>
#include <cuda_fp16.h>

// ---------------- problem constants ----------------
#define BB   2
#define CC   24
#define KQ   7
#define KK   49
#define HH   256
#define WW   256
#define CO   1176          // CC*KK
#define PLANE 65536
#define NPIX  131072

#define LOG2E 1.4426950408889634f

// ---------------- device scratch ----------------
__device__ __half g_E[(size_t)CO * NPIX];  // unnormalized exp(logits), fp16, plane-major
__device__ float g_Sinv[NPIX];
__device__ float g_lat[BB * CC * PLANE];
__device__ float g_dA[BB * CC * PLANE];
__device__ float g_dB[BB * CC * PLANE];

// ---------------- packed f32x2 helpers ----------------
typedef unsigned long long ull;
__device__ __forceinline__ ull pk2(float lo, float hi) {
    ull r; asm("mov.b64 %0, {%1, %2};" : "=l"(r) : "f"(lo), "f"(hi)); return r;
}
__device__ __forceinline__ void fma2(ull& d, ull a, ull b) {
    asm("fma.rn.f32x2 %0, %1, %2, %0;" : "+l"(d) : "l"(a), "l"(b));
}
__device__ __forceinline__ void add2(ull& d, ull a) {
    asm("add.rn.f32x2 %0, %0, %1;" : "+l"(d) : "l"(a));
}
__device__ __forceinline__ ull mul2(ull a, ull b) {
    ull r; asm("mul.rn.f32x2 %0, %1, %2;" : "=l"(r) : "l"(a), "l"(b)); return r;
}
__device__ __forceinline__ void unpk2(float& lo, float& hi, ull v) {
    asm("mov.b64 {%0, %1}, %2;" : "=f"(lo), "=f"(hi) : "l"(v));
}
__device__ __forceinline__ float ex2(float x) {
    float r; asm("ex2.approx.f32 %0, %1;" : "=f"(r) : "f"(x)); return r;
}
__device__ __forceinline__ float rcpf(float x) {
    float r; asm("rcp.approx.f32 %0, %1;" : "=f"(r) : "f"(x)); return r;
}

// ================= K1: depth_latent = conv3x3(depth; 1 -> 24) =================
__global__ void k_lat(const float* __restrict__ depth,
                      const float* __restrict__ w_dp,
                      const float* __restrict__ b_dp) {
    __shared__ float sD[3][WW + 2];
    __shared__ float sW[CC * 9];
    __shared__ float sB[CC];
    const int bid = blockIdx.x;
    const int b = bid >> 8, y = bid & 255;
    const int tid = threadIdx.x;

    for (int i = tid; i < CC * 9; i += blockDim.x) sW[i] = w_dp[i];
    if (tid < CC) sB[tid] = b_dp[tid];

    const float* dp = depth + (size_t)b * PLANE;
    for (int r = 0; r < 3; r++) {
        const int yy = y + r - 1;
        for (int xx = tid; xx < WW + 2; xx += blockDim.x) {
            const int gx = xx - 1;
            sD[r][xx] = (yy >= 0 && yy < HH && gx >= 0 && gx < WW) ? dp[yy * WW + gx] : 0.f;
        }
    }
    __syncthreads();

    float p[9];
#pragma unroll
    for (int r = 0; r < 3; r++)
#pragma unroll
        for (int cx = 0; cx < 3; cx++) p[r * 3 + cx] = sD[r][tid + cx];

    for (int co = 0; co < CC; co++) {
        float acc = sB[co];
#pragma unroll
        for (int j = 0; j < 9; j++) acc = fmaf(sW[co * 9 + j], p[j], acc);
        g_lat[((size_t)(b * CC + co) * HH + y) * WW + tid] = acc;
    }
}

// ================= K2: logits conv (3->1176) + exp (fp16 out) + per-pixel sum =================
// Block = 2 image rows, 128 threads. Thread t: row ri = t>>6, 4 pixels x0..x0+3,
// x0 = 4*(t&63). Two f32x2 streams (pixel pairs A=(x0,x0+1), B=(x0+2,x0+3))
// share every weight fetch. Weights staged duplicated (w,w), pre-scaled by log2(e).
#define OCHUNK 147           // 1176/147 = 8 chunks
__global__ __launch_bounds__(128) void k_softmax(const float* __restrict__ tex,
                                                 const float* __restrict__ w_kp,
                                                 const float* __restrict__ b_kp) {
    __shared__ __align__(16) float2 sW2[OCHUNK * 28];  // (w,w) pairs, 27 + zero-pad
    __shared__ float sB[OCHUNK];
    __shared__ float sT[3][4][WW + 2];                  // 3 ch x 4 rows (y0-1..y0+2)

    const int bid = blockIdx.x;          // 0..BB*HH/2-1
    const int b = bid >> 7;
    const int y0 = (bid & 127) * 2;
    const int tid = threadIdx.x;
    const int ri = tid >> 6;             // 0/1 row within block
    const int x0 = (tid & 63) * 4;

    // stage texture rows y0-1 .. y0+2 (zero-padded)
    for (int ch = 0; ch < 3; ch++) {
        const float* tp = tex + (size_t)(b * 3 + ch) * PLANE;
        for (int rr = 0; rr < 4; rr++) {
            const int yy = y0 + rr - 1;
            for (int xx = tid; xx < WW + 2; xx += blockDim.x) {
                const int gx = xx - 1;
                sT[ch][rr][xx] = (yy >= 0 && yy < HH && gx >= 0 && gx < WW) ? tp[yy * WW + gx] : 0.f;
            }
        }
    }
    __syncthreads();

    // Build packed patch pairs. For (ch,r): v[k] = img col (x0-1+k), k=0..5.
    // pairA(cx) = (v[cx],v[cx+1]), pairB(cx) = (v[cx+2],v[cx+3]).
    ull PK[3][3][5];
#pragma unroll
    for (int ch = 0; ch < 3; ch++)
#pragma unroll
        for (int r = 0; r < 3; r++) {
            float v[6];
#pragma unroll
            for (int k = 0; k < 6; k++) v[k] = sT[ch][ri + r][x0 + k];
#pragma unroll
            for (int k = 0; k < 5; k++) PK[ch][r][k] = pk2(v[k], v[k + 1]);
        }
    const ull ZP = pk2(0.f, 0.f);

    float S0 = 0.f, S1 = 0.f, S2 = 0.f, S3 = 0.f;
    const size_t pixbase = (size_t)b * PLANE + (size_t)(y0 + ri) * WW + x0;  // mult of 4

    for (int ochunk = 0; ochunk < CO; ochunk += OCHUNK) {
        __syncthreads();
        for (int i = tid; i < OCHUNK * 28; i += blockDim.x) {
            const int o = i / 28, j = i - o * 28;
            const float w = (j < 27) ? w_kp[(size_t)(ochunk + o) * 27 + j] * LOG2E : 0.f;
            sW2[i] = make_float2(w, w);
        }
        for (int i = tid; i < OCHUNK; i += blockDim.x) sB[i] = b_kp[ochunk + i] * LOG2E;
        __syncthreads();

        for (int ol = 0; ol < OCHUNK; ol++) {
            const float4* w4 = reinterpret_cast<const float4*>(&sW2[ol * 28]);
            const float bb = sB[ol];
            ull aA0 = pk2(bb, bb), aA1 = ZP;
            ull aB0 = pk2(bb, bb), aB1 = ZP;
#pragma unroll
            for (int q = 0; q < 14; q++) {
                const float4 v = w4[q];
                const ull wp0 = pk2(v.x, v.y);
                const ull wp1 = pk2(v.z, v.w);
                const int j0 = 2 * q, j1 = 2 * q + 1;
                const ull pA0 = (j0 < 27) ? PK[j0 / 9][(j0 % 9) / 3][j0 % 3] : ZP;
                const ull pB0 = (j0 < 27) ? PK[j0 / 9][(j0 % 9) / 3][j0 % 3 + 2] : ZP;
                const ull pA1 = (j1 < 27) ? PK[j1 / 9][(j1 % 9) / 3][j1 % 3] : ZP;
                const ull pB1 = (j1 < 27) ? PK[j1 / 9][(j1 % 9) / 3][j1 % 3 + 2] : ZP;
                fma2(aA0, wp0, pA0);
                fma2(aB0, wp0, pB0);
                fma2(aA1, wp1, pA1);
                fma2(aB1, wp1, pB1);
            }
            add2(aA0, aA1);
            add2(aB0, aB1);
            float lA0, lA1, lB0, lB1;
            unpk2(lA0, lA1, aA0);
            unpk2(lB0, lB1, aB0);
            const float eA0 = ex2(lA0), eA1 = ex2(lA1);
            const float eB0 = ex2(lB0), eB1 = ex2(lB1);
            S0 += eA0; S1 += eA1; S2 += eB0; S3 += eB1;
            const __half2 hA = __floats2half2_rn(eA0, eA1);
            const __half2 hB = __floats2half2_rn(eB0, eB1);
            uint2 st;
            st.x = *reinterpret_cast<const unsigned int*>(&hA);
            st.y = *reinterpret_cast<const unsigned int*>(&hB);
            *reinterpret_cast<uint2*>(&g_E[(size_t)(ochunk + ol) * NPIX + pixbase]) = st;
        }
    }
    float4 si;
    si.x = rcpf(S0); si.y = rcpf(S1); si.z = rcpf(S2); si.w = rcpf(S3);
    *reinterpret_cast<float4*>(&g_Sinv[pixbase]) = si;
}

// ================= K3..K6: one diffusion iteration =================
// 128 threads; thread handles pixel pair (2t, 2t+1). E via half2 LDG.32,
// depth taps via aligned LDS.64 (second 1-shifted smem copy for odd dx),
// MAC via fma.rn.f32x2.
#define RROWS 8
__global__ __launch_bounds__(128) void k_diff(int srcSel, int dstSel) {
    __shared__ __align__(16) float sIn[RROWS + 6][WW + 8];
    __shared__ __align__(16) float sInS[RROWS + 6][WW + 8];   // sInS[r][x] = sIn[r][x+1]
    const int tid = threadIdx.x;
    const int x0 = 2 * tid;
    const int ty = blockIdx.x;
    const int c = blockIdx.y;
    const int b = blockIdx.z;
    const int y0 = ty * RROWS;

    const float* src = (srcSel == 0) ? g_lat : (srcSel == 1 ? g_dA : g_dB);
    float* dst = (dstSel == 1) ? g_dA : g_dB;

    const float* sp = src + (size_t)(b * CC + c) * PLANE;
    for (int r = 0; r < RROWS + 6; r++) {
        const int yy = y0 + r - 3;
        for (int xx = tid; xx < WW + 6; xx += blockDim.x) {
            const int gx = xx - 3;
            const float v = (yy >= 0 && yy < HH && gx >= 0 && gx < WW) ? sp[yy * WW + gx] : 0.f;
            sIn[r][xx] = v;
            if (xx > 0) sInS[r][xx - 1] = v;
        }
    }
    __syncthreads();

    const __half* Ebase = g_E + (size_t)(c * KK) * NPIX + (size_t)b * PLANE + (size_t)y0 * WW + x0;
    const float* Sp = g_Sinv + (size_t)b * PLANE + (size_t)y0 * WW + x0;
    float* dp = dst + ((size_t)(b * CC + c) * HH + y0) * WW + x0;

    for (int ry = 0; ry < RROWS; ry++) {
        const __half* Ep = Ebase + (size_t)ry * WW;
        ull acc0 = pk2(0.f, 0.f), acc1 = pk2(0.f, 0.f);
#pragma unroll
        for (int t = 0; t < KK; t++) {
            const int dy = t / KQ, dx = t % KQ;
            const __half2 h = *reinterpret_cast<const __half2*>(Ep + (size_t)t * NPIX);
            const ull ev = pk2(__low2float(h), __high2float(h));
            float2 dv;
            if (((x0 + dx) & 1) == 0)
                dv = *reinterpret_cast<const float2*>(&sIn[ry + dy][x0 + dx]);
            else
                dv = *reinterpret_cast<const float2*>(&sInS[ry + dy][x0 + dx - 1]);
            if (t & 1) fma2(acc1, ev, pk2(dv.x, dv.y));
            else       fma2(acc0, ev, pk2(dv.x, dv.y));
        }
        add2(acc0, acc1);
        const float2 si = *reinterpret_cast<const float2*>(Sp + (size_t)ry * WW);
        const ull r = mul2(acc0, pk2(si.x, si.y));
        float o0, o1;
        unpk2(o0, o1, r);
        *reinterpret_cast<float2*>(dp + (size_t)ry * WW) = make_float2(o0, o1);
    }
}

// ================= K7: 1x1 conv (24 -> 1) =================
__global__ void k_out(const float* __restrict__ w_td,
                      const float* __restrict__ b_td,
                      float* __restrict__ out) {
    const int bid = blockIdx.x;
    const int b = bid >> 8, y = bid & 255;
    const int tid = threadIdx.x;
    const float* sp = g_dB + (size_t)b * CC * PLANE + (size_t)y * WW + tid;
    float acc = b_td[0];
#pragma unroll
    for (int c = 0; c < CC; c++) acc = fmaf(w_td[c], sp[(size_t)c * PLANE], acc);
    out[(size_t)b * PLANE + (size_t)y * WW + tid] = acc;
}

// ================= host launcher =================
extern "C" void kernel_launch(void* const* d_in, const int* in_sizes, int n_in,
                              void* d_out, int out_size) {
    const float* depth   = (const float*)d_in[0];
    const float* texture = (const float*)d_in[1];
    const float* w_dp    = (const float*)d_in[2];
    const float* b_dp    = (const float*)d_in[3];
    const float* w_kp    = (const float*)d_in[4];
    const float* b_kp    = (const float*)d_in[5];
    const float* w_td    = (const float*)d_in[6];
    const float* b_td    = (const float*)d_in[7];
    float* out = (float*)d_out;

    k_lat<<<BB * HH, 256>>>(depth, w_dp, b_dp);
    k_softmax<<<BB * HH / 2, 128>>>(texture, w_kp, b_kp);

    dim3 gd(HH / RROWS, CC, BB);
    k_diff<<<gd, 128>>>(0, 1);
    k_diff<<<gd, 128>>>(1, 2);
    k_diff<<<gd, 128>>>(2, 1);
    k_diff<<<gd, 128>>>(1, 2);

    k_out<<<BB * HH, 256>>>(w_td, b_td, out);
}

// round 5
// speedup vs baseline: 1.2765x; 1.0506x over previous
#include <cuda_runtime.h>
#include <cuda_fp16.h>

// ---------------- problem constants ----------------
#define BB   2
#define CC   24
#define KQ   7
#define KK   49
#define HH   256
#define WW   256
#define CO   1176          // CC*KK
#define PLANE 65536
#define NPIX  131072

#define LOG2E 1.4426950408889634f

// ---------------- device scratch ----------------
__device__ __half g_E[(size_t)CO * NPIX];   // unnormalized exp(logits), fp16, plane-major
__device__ float g_Spart[(size_t)CC * NPIX];// per-channel partial softmax sums
__device__ float g_Sinv[NPIX];
__device__ float g_lat[BB * CC * PLANE];
__device__ float g_dA[BB * CC * PLANE];
__device__ float g_dB[BB * CC * PLANE];

// ---------------- packed f32x2 helpers ----------------
typedef unsigned long long ull;
__device__ __forceinline__ ull pk2(float lo, float hi) {
    ull r; asm("mov.b64 %0, {%1, %2};" : "=l"(r) : "f"(lo), "f"(hi)); return r;
}
__device__ __forceinline__ void fma2(ull& d, ull a, ull b) {
    asm("fma.rn.f32x2 %0, %1, %2, %0;" : "+l"(d) : "l"(a), "l"(b));
}
__device__ __forceinline__ void add2(ull& d, ull a) {
    asm("add.rn.f32x2 %0, %0, %1;" : "+l"(d) : "l"(a));
}
__device__ __forceinline__ ull mul2(ull a, ull b) {
    ull r; asm("mul.rn.f32x2 %0, %1, %2;" : "=l"(r) : "l"(a), "l"(b)); return r;
}
__device__ __forceinline__ void unpk2(float& lo, float& hi, ull v) {
    asm("mov.b64 {%0, %1}, %2;" : "=f"(lo), "=f"(hi) : "l"(v));
}
__device__ __forceinline__ float ex2(float x) {
    float r; asm("ex2.approx.f32 %0, %1;" : "=f"(r) : "f"(x)); return r;
}
__device__ __forceinline__ float rcpf(float x) {
    float r; asm("rcp.approx.f32 %0, %1;" : "=f"(r) : "f"(x)); return r;
}

// ================= K1: depth_latent = conv3x3(depth; 1 -> 24) =================
__global__ void k_lat(const float* __restrict__ depth,
                      const float* __restrict__ w_dp,
                      const float* __restrict__ b_dp) {
    __shared__ float sD[3][WW + 2];
    __shared__ float sW[CC * 9];
    __shared__ float sB[CC];
    const int bid = blockIdx.x;
    const int b = bid >> 8, y = bid & 255;
    const int tid = threadIdx.x;

    for (int i = tid; i < CC * 9; i += blockDim.x) sW[i] = w_dp[i];
    if (tid < CC) sB[tid] = b_dp[tid];

    const float* dp = depth + (size_t)b * PLANE;
    for (int r = 0; r < 3; r++) {
        const int yy = y + r - 1;
        for (int xx = tid; xx < WW + 2; xx += blockDim.x) {
            const int gx = xx - 1;
            sD[r][xx] = (yy >= 0 && yy < HH && gx >= 0 && gx < WW) ? dp[yy * WW + gx] : 0.f;
        }
    }
    __syncthreads();

    float p[9];
#pragma unroll
    for (int r = 0; r < 3; r++)
#pragma unroll
        for (int cx = 0; cx < 3; cx++) p[r * 3 + cx] = sD[r][tid + cx];

    for (int co = 0; co < CC; co++) {
        float acc = sB[co];
#pragma unroll
        for (int j = 0; j < 9; j++) acc = fmaf(sW[co * 9 + j], p[j], acc);
        g_lat[((size_t)(b * CC + co) * HH + y) * WW + tid] = acc;
    }
}

// ================= K2: logits conv (3->1176) + exp (fp16 out) + partial sums ==========
// grid = (BB*HH/2 row-pairs, CC channels). Block computes its channel's 49 outputs.
// Thread t: row ri = t>>6, pixels x0..x0+3, x0 = 4*(t&63). Two f32x2 streams share
// every weight fetch. Weights duplicated (w,w), pre-scaled by log2(e).
__global__ __launch_bounds__(128) void k_softmax(const float* __restrict__ tex,
                                                 const float* __restrict__ w_kp,
                                                 const float* __restrict__ b_kp) {
    __shared__ __align__(16) float2 sW2[KK * 28];   // (w,w) pairs, 27 + zero-pad
    __shared__ float sB[KK];
    __shared__ float sT[3][4][WW + 2];

    const int bid = blockIdx.x;          // 0..BB*HH/2-1
    const int c = blockIdx.y;            // channel 0..23
    const int b = bid >> 7;
    const int y0 = (bid & 127) * 2;
    const int tid = threadIdx.x;
    const int ri = tid >> 6;
    const int x0 = (tid & 63) * 4;

    // stage this channel's 49x27 weights, duplicated + log2e-scaled
    for (int i = tid; i < KK * 28; i += 128) {
        const int o = i / 28, j = i - o * 28;
        const float w = (j < 27) ? w_kp[(size_t)(c * KK + o) * 27 + j] * LOG2E : 0.f;
        sW2[i] = make_float2(w, w);
    }
    if (tid < KK) sB[tid] = b_kp[c * KK + tid] * LOG2E;

    // stage texture rows y0-1 .. y0+2 (zero-padded)
    for (int ch = 0; ch < 3; ch++) {
        const float* tp = tex + (size_t)(b * 3 + ch) * PLANE;
        for (int rr = 0; rr < 4; rr++) {
            const int yy = y0 + rr - 1;
            for (int xx = tid; xx < WW + 2; xx += blockDim.x) {
                const int gx = xx - 1;
                sT[ch][rr][xx] = (yy >= 0 && yy < HH && gx >= 0 && gx < WW) ? tp[yy * WW + gx] : 0.f;
            }
        }
    }
    __syncthreads();

    // packed patch pairs: v[k] = img col (x0-1+k), pairs (v[k],v[k+1]) k=0..4
    ull PK[3][3][5];
#pragma unroll
    for (int ch = 0; ch < 3; ch++)
#pragma unroll
        for (int r = 0; r < 3; r++) {
            float v[6];
#pragma unroll
            for (int k = 0; k < 6; k++) v[k] = sT[ch][ri + r][x0 + k];
#pragma unroll
            for (int k = 0; k < 5; k++) PK[ch][r][k] = pk2(v[k], v[k + 1]);
        }
    const ull ZP = pk2(0.f, 0.f);

    float S0 = 0.f, S1 = 0.f, S2 = 0.f, S3 = 0.f;
    const size_t pixbase = (size_t)b * PLANE + (size_t)(y0 + ri) * WW + x0;  // mult of 4

#pragma unroll 1
    for (int ol = 0; ol < KK; ol++) {
        const float4* w4 = reinterpret_cast<const float4*>(&sW2[ol * 28]);
        const float bb = sB[ol];
        ull aA0 = pk2(bb, bb), aA1 = ZP;
        ull aB0 = pk2(bb, bb), aB1 = ZP;
#pragma unroll
        for (int q = 0; q < 14; q++) {
            const float4 v = w4[q];
            const ull wp0 = pk2(v.x, v.y);
            const ull wp1 = pk2(v.z, v.w);
            const int j0 = 2 * q, j1 = 2 * q + 1;
            const ull pA0 = (j0 < 27) ? PK[j0 / 9][(j0 % 9) / 3][j0 % 3] : ZP;
            const ull pB0 = (j0 < 27) ? PK[j0 / 9][(j0 % 9) / 3][j0 % 3 + 2] : ZP;
            const ull pA1 = (j1 < 27) ? PK[j1 / 9][(j1 % 9) / 3][j1 % 3] : ZP;
            const ull pB1 = (j1 < 27) ? PK[j1 / 9][(j1 % 9) / 3][j1 % 3 + 2] : ZP;
            fma2(aA0, wp0, pA0);
            fma2(aB0, wp0, pB0);
            fma2(aA1, wp1, pA1);
            fma2(aB1, wp1, pB1);
        }
        add2(aA0, aA1);
        add2(aB0, aB1);
        float lA0, lA1, lB0, lB1;
        unpk2(lA0, lA1, aA0);
        unpk2(lB0, lB1, aB0);
        const float eA0 = ex2(lA0), eA1 = ex2(lA1);
        const float eB0 = ex2(lB0), eB1 = ex2(lB1);
        S0 += eA0; S1 += eA1; S2 += eB0; S3 += eB1;
        const __half2 hA = __floats2half2_rn(eA0, eA1);
        const __half2 hB = __floats2half2_rn(eB0, eB1);
        uint2 st;
        st.x = *reinterpret_cast<const unsigned int*>(&hA);
        st.y = *reinterpret_cast<const unsigned int*>(&hB);
        *reinterpret_cast<uint2*>(&g_E[(size_t)(c * KK + ol) * NPIX + pixbase]) = st;
    }
    float4 ps;
    ps.x = S0; ps.y = S1; ps.z = S2; ps.w = S3;
    *reinterpret_cast<float4*>(&g_Spart[(size_t)c * NPIX + pixbase]) = ps;
}

// ================= K2b: reduce 24 partials -> 1/S =================
__global__ void k_sinv() {
    const int idx = blockIdx.x * 256 + threadIdx.x;
    float s = 0.f;
#pragma unroll
    for (int c = 0; c < CC; c++) s += g_Spart[(size_t)c * NPIX + idx];
    g_Sinv[idx] = rcpf(s);
}

// ================= K3..K6: one diffusion iteration =================
// 128 threads; thread handles 4 pixels (x0 = 4*(tid&63)), 2 rows in flight per pass.
// E via uint2 LDG.64 (4 halves), taps via 3 aligned LDS.128 per (dy,row).
#define RROWS 8
__global__ __launch_bounds__(128) void k_diff(int srcSel, int dstSel) {
    __shared__ __align__(16) float sIn[RROWS + 6][WW + 16];   // sIn[r][xx] = in(y0+r-3, xx-4)
    const int tid = threadIdx.x;
    const int ty = blockIdx.x;
    const int c = blockIdx.y;
    const int b = blockIdx.z;
    const int y0 = ty * RROWS;

    const float* src = (srcSel == 0) ? g_lat : (srcSel == 1 ? g_dA : g_dB);
    float* dst = (dstSel == 1) ? g_dA : g_dB;

    const float* sp = src + (size_t)(b * CC + c) * PLANE;
    for (int r = 0; r < RROWS + 6; r++) {
        const int yy = y0 + r - 3;
        for (int xx = tid; xx < WW + 12; xx += 128) {
            const int gx = xx - 4;
            sIn[r][xx] = (yy >= 0 && yy < HH && gx >= 0 && gx < WW) ? sp[yy * WW + gx] : 0.f;
        }
    }
    __syncthreads();

    const int ri = tid >> 6;
    const int x0 = (tid & 63) * 4;
    const __half* Eb = g_E + (size_t)(c * KK) * NPIX + (size_t)b * PLANE;
    const float* Sb = g_Sinv + (size_t)b * PLANE;
    float* db = dst + (size_t)(b * CC + c) * PLANE;

#pragma unroll
    for (int pass = 0; pass < RROWS / 2; pass++) {
        const int ry = pass * 2 + ri;
        const size_t rowoff = (size_t)(y0 + ry) * WW + x0;
        const __half* Ep = Eb + rowoff;

        ull a0 = pk2(0.f, 0.f), a1 = a0, a2 = a0, a3 = a0;
#pragma unroll
        for (int dy = 0; dy < KQ; dy++) {
            const float4 v0 = *reinterpret_cast<const float4*>(&sIn[ry + dy][x0]);
            const float4 v1 = *reinterpret_cast<const float4*>(&sIn[ry + dy][x0 + 4]);
            const float4 v2 = *reinterpret_cast<const float4*>(&sIn[ry + dy][x0 + 8]);
            const float f1 = v0.y, f2 = v0.z, f3 = v0.w;
            const float f4 = v1.x, f5 = v1.y, f6 = v1.z, f7 = v1.w;
            const float f8 = v2.x, f9 = v2.y, f10 = v2.z;
            ull pr[9];
            pr[0] = pk2(f1, f2);  pr[1] = pk2(f2, f3);  pr[2] = pk2(f3, f4);
            pr[3] = pk2(f4, f5);  pr[4] = pk2(f5, f6);  pr[5] = pk2(f6, f7);
            pr[6] = pk2(f7, f8);  pr[7] = pk2(f8, f9);  pr[8] = pk2(f9, f10);
#pragma unroll
            for (int dx = 0; dx < KQ; dx++) {
                const int t = dy * KQ + dx;
                const uint2 e = *reinterpret_cast<const uint2*>(Ep + (size_t)t * NPIX);
                __half2 hA, hB;
                *reinterpret_cast<unsigned int*>(&hA) = e.x;
                *reinterpret_cast<unsigned int*>(&hB) = e.y;
                const float2 fA = __half22float2(hA);
                const float2 fB = __half22float2(hB);
                if (dx & 1) {
                    fma2(a1, pk2(fA.x, fA.y), pr[dx]);
                    fma2(a3, pk2(fB.x, fB.y), pr[dx + 2]);
                } else {
                    fma2(a0, pk2(fA.x, fA.y), pr[dx]);
                    fma2(a2, pk2(fB.x, fB.y), pr[dx + 2]);
                }
            }
        }
        add2(a0, a1);
        add2(a2, a3);
        const float4 si = *reinterpret_cast<const float4*>(Sb + rowoff);
        const ull rA = mul2(a0, pk2(si.x, si.y));
        const ull rB = mul2(a2, pk2(si.z, si.w));
        float4 o;
        unpk2(o.x, o.y, rA);
        unpk2(o.z, o.w, rB);
        *reinterpret_cast<float4*>(db + rowoff) = o;
    }
}

// ================= K7: 1x1 conv (24 -> 1) =================
__global__ void k_out(const float* __restrict__ w_td,
                      const float* __restrict__ b_td,
                      float* __restrict__ out) {
    const int bid = blockIdx.x;
    const int b = bid >> 8, y = bid & 255;
    const int tid = threadIdx.x;
    const float* sp = g_dB + (size_t)b * CC * PLANE + (size_t)y * WW + tid;
    float acc = b_td[0];
#pragma unroll
    for (int c = 0; c < CC; c++) acc = fmaf(w_td[c], sp[(size_t)c * PLANE], acc);
    out[(size_t)b * PLANE + (size_t)y * WW + tid] = acc;
}

// ================= host launcher =================
extern "C" void kernel_launch(void* const* d_in, const int* in_sizes, int n_in,
                              void* d_out, int out_size) {
    const float* depth   = (const float*)d_in[0];
    const float* texture = (const float*)d_in[1];
    const float* w_dp    = (const float*)d_in[2];
    const float* b_dp    = (const float*)d_in[3];
    const float* w_kp    = (const float*)d_in[4];
    const float* b_kp    = (const float*)d_in[5];
    const float* w_td    = (const float*)d_in[6];
    const float* b_td    = (const float*)d_in[7];
    float* out = (float*)d_out;

    k_lat<<<BB * HH, 256>>>(depth, w_dp, b_dp);

    dim3 gs(BB * HH / 2, CC);
    k_softmax<<<gs, 128>>>(texture, w_kp, b_kp);
    k_sinv<<<NPIX / 256, 256>>>();

    dim3 gd(HH / RROWS, CC, BB);
    k_diff<<<gd, 128>>>(0, 1);
    k_diff<<<gd, 128>>>(1, 2);
    k_diff<<<gd, 128>>>(2, 1);
    k_diff<<<gd, 128>>>(1, 2);

    k_out<<<BB * HH, 256>>>(w_td, b_td, out);
}